// round 15
// baseline (speedup 1.0000x reference)
#include <cuda_runtime.h>
#include <cstdint>

#define NB 64
#define C  128
#define H  56
#define W  56
#define HW 3136
#define PROW 58
#define PIMG 3364
#define IMG_ROWS 3584
#define GUARD 128
#define TOT_ROWS (GUARD + NB*IMG_ROWS)
#define TPI 27
#define NTT (NB*TPI)                  // 1728 tensor tiles
#define NPAIR (NB*28)                 // 1792 scalar row-pairs
#define GRID_CONV 148
#define ROWB 144
#define NCT 40                        // tensor co count (co 0..39)
#define NCS 88                        // scalar co count (co 40..127)
#define NTHREADS 768                  // 4 tensor warps + 20 scalar warps

// smem offsets (bytes)
#define SM_B    0                     // 9*40*ROWB = 51840
#define ABUF    35424                 // one A buffer: 246*ROWB
#define SM_A    51840                 // 2 buffers = 70848
#define SM_W    122688                // 88*9*16 = 12672
#define XBUF    3712                  // one X buffer: 4*58*16
#define SM_X    135360                // 2 buffers = 7424
#define SM_CC   142784                // 3*88*16 = 4224
#define SM_Q2   147008                // 3*88*4 = 1056
#define SM_ABN  148064                // 40*2*4 = 320
#define SMEM_TOTAL 148384

// NOTE: no zero_kernel — static __device__ globals are zero-initialized at
// module load, and interior writes below never touch pad/guard/tail rows.
__device__ __align__(1024) unsigned char g_spad[(size_t)TOT_ROWS * 128]; // s8 signs, k-permuted
__device__ __align__(16)   unsigned char g_bs8[9 * NCT * 128];           // [tap][co<40][ci'] s8
__device__ __align__(16)   uint32_t g_wbits[C * 9 * 4];                  // bitmask [co][tap][word]
__device__ float g_A[C], g_Bc[C], g_wcnt[C * 9];
__device__ uint4 g_xbits[NB * HW];

__host__ __device__ __forceinline__ int permw(int w) {
    int ww = w & 7;
    return (w & ~7) | ((ww < 4) ? (ww << 1) : (((ww - 4) << 1) | 1));
}
__device__ __forceinline__ uint32_t smem_u32(const void* p) {
    uint32_t a;
    asm("{ .reg .u64 t; cvta.to.shared.u64 t, %1; cvt.u32.u64 %0, t; }" : "=r"(a) : "l"(p));
    return a;
}
__device__ __forceinline__ void fadd(uint32_t a, uint32_t b, uint32_t c,
                                     uint32_t& s, uint32_t& cy) {
    s = a ^ b ^ c; cy = (a & b) | (c & (a ^ b));
}
__device__ __forceinline__ void cpa16(uint32_t d, const void* s) {
    asm volatile("cp.async.cg.shared.global [%0], [%1], 16;" :: "r"(d), "l"(s));
}
__device__ __forceinline__ void cpa16z(uint32_t d, const void* s, int sz) {
    asm volatile("cp.async.cg.shared.global [%0], [%1], 16, %2;" :: "r"(d), "l"(s), "r"(sz));
}
#define CPA_COMMIT() asm volatile("cp.async.commit_group;" ::: "memory")
#define CPA_WAIT1()  asm volatile("cp.async.wait_group 1;" ::: "memory")
#define CPA_WAIT0()  asm volatile("cp.async.wait_group 0;" ::: "memory")

// ---------------- Kernel 1: x -> s8 spad (permuted) + bitpacked xbits ----------------
__global__ void sign_kernel(const float* __restrict__ x) {
    __shared__ uint32_t s[56][33];
    int nb = blockIdx.x;
    int n = nb / H, h = nb - n * H;
    int t = threadIdx.x;
    const float* xp = x + (size_t)n * C * HW + (size_t)h * W;
    for (int it = t; it < 56 * 32; it += 256) {
        int w = it % 56, cg = it / 56;
        uint32_t b = 0;
#pragma unroll
        for (int j = 0; j < 4; j++) {
            float v = __ldg(xp + (size_t)(cg * 4 + j) * HW + w);
            b |= ((v < 0.0f) ? 0xFFu : 0x01u) << (j * 8);
        }
        s[w][cg] = b;
    }
    __syncthreads();
    uint32_t* dst = (uint32_t*)(g_spad +
        ((size_t)GUARD + (size_t)n * IMG_ROWS + (size_t)(h + 1) * PROW + 1) * 128);
    for (int it = t; it < 56 * 32; it += 256) {
        int pix = it >> 5, l = it & 31;
        dst[(size_t)pix * 32 + permw(l)] = s[pix][l];
    }
    if (t < 224) {
        int w = t >> 2, j = t & 3;
        uint32_t b = 0;
#pragma unroll
        for (int m = 0; m < 8; m++) {
            uint32_t sv = s[w][j * 8 + m];
#pragma unroll
            for (int k = 0; k < 4; k++)
                b |= ((sv >> (8 * k + 7)) & 1u) << (m * 4 + k);
        }
        ((uint32_t*)&g_xbits[(size_t)n * HW + h * W + w])[j] = b;
    }
}

// ---------------- Kernel 2: parallel weight prep (grid = 128 co, 128 thr) ----------------
__global__ void wprep_kernel(const float* __restrict__ wgt,
                             const float* __restrict__ gamma,
                             const float* __restrict__ beta,
                             const float* __restrict__ mean,
                             const float* __restrict__ var) {
    __shared__ float s_abs[4];
    __shared__ int   s_pc[9][4];
    int co = blockIdx.x;
    int t  = threadIdx.x;          // = ci
    int lane = t & 31, j = t >> 5;

    float v[9];
    const float* wp = wgt + (size_t)co * 1152 + (size_t)t * 9;
    float sabs = 0.0f;
#pragma unroll
    for (int tap = 0; tap < 9; tap++) { v[tap] = wp[tap]; sabs += fabsf(v[tap]); }
#pragma unroll
    for (int o = 16; o > 0; o >>= 1) sabs += __shfl_xor_sync(0xffffffffu, sabs, o);
    if (lane == 0) s_abs[j] = sabs;

    int pci = permw(t >> 2) * 4 + (t & 3);
#pragma unroll
    for (int tap = 0; tap < 9; tap++) {
        uint32_t wb = __ballot_sync(0xffffffffu, v[tap] < 0.0f);
        if (lane == 0) {
            g_wbits[(co * 9 + tap) * 4 + j] = wb;
            s_pc[tap][j] = __popc(wb);
        }
        if (co < NCT)
            g_bs8[((size_t)tap * NCT + co) * 128 + pci] = (v[tap] < 0.0f) ? 0xFF : 0x01;
    }
    __syncthreads();
    if (t < 9)
        g_wcnt[co * 9 + t] = (float)(s_pc[t][0] + s_pc[t][1] + s_pc[t][2] + s_pc[t][3]);
    if (t == 0) {
        float tot = s_abs[0] + s_abs[1] + s_abs[2] + s_abs[3];
        float scale = tot * (1.0f / 1152.0f);
        float inv = gamma[co] * rsqrtf(var[co] + 1e-5f);
        g_A[co]  = scale * inv;
        g_Bc[co] = beta[co] - mean[co] * inv;
    }
}

// ---------------- Kernel 3: hybrid conv, 24 warps (4 tensor + 20 scalar) ----------------
__global__ void __launch_bounds__(NTHREADS, 1)
conv_kernel(const float* __restrict__ x, float* __restrict__ out) {
    extern __shared__ unsigned char smem[];
    const int tid = threadIdx.x;
    const int warp = tid >> 5;
    const int lane = tid & 31;
    const int cta = blockIdx.x;
    const uint32_t sb = smem_u32(smem);

    // ---- shared staging (all threads) ----
    for (int i = tid; i < 9 * NCT * 8; i += NTHREADS) {
        int r = i >> 3, j = i & 7;
        *(uint4*)(smem + SM_B + r * ROWB + j * 16) = ((const uint4*)(g_bs8 + (size_t)r * 128))[j];
    }
    {
        const uint4* gw = (const uint4*)g_wbits;
        for (int i = tid; i < NCS * 9; i += NTHREADS)
            ((uint4*)(smem + SM_W))[i] = gw[NCT * 9 + i];
    }
    for (int i = tid; i < 3 * NCS; i += NTHREADS) {
        int cl = i / NCS, co = NCT + (i - cl * NCS);
        float A = g_A[co], Bv = g_Bc[co];
        float wc[9];
#pragma unroll
        for (int t = 0; t < 9; t++) wc[t] = g_wcnt[co * 9 + t];
        float cr = (cl == 0 ? wc[0] + wc[1] + wc[2] : 0.0f)
                 + (cl == 2 ? wc[6] + wc[7] + wc[8] : 0.0f);
        float c0 = (cl == 0 ? 0.0f : wc[0]) + wc[3] + (cl == 2 ? 0.0f : wc[6]);
        float c2 = (cl == 0 ? 0.0f : wc[2]) + wc[5] + (cl == 2 ? 0.0f : wc[8]);
        ((float4*)(smem + SM_CC))[i] = make_float4(-2.0f * A, A, fmaf(2.0f * A, cr, Bv), 2.0f * A * c0);
        ((float*)(smem + SM_Q2))[i] = 2.0f * A * c2;
    }
    if (tid < NCT) {
        ((float*)(smem + SM_ABN))[tid] = g_A[tid];
        ((float*)(smem + SM_ABN))[NCT + tid] = g_Bc[tid];
    }
    __syncthreads();

    if (warp < 4) {
        // ================= TENSOR GROUP: 4 warps, co 0..39 =================
        const int g = lane >> 2, tg = lane & 3;
        const int m0 = warp * 32;
        const int t0 = (int)(((long)cta * NTT) / GRID_CONV);
        const int t1 = (int)(((long)(cta + 1) * NTT) / GRID_CONV);
        const float* abn = (const float*)(smem + SM_ABN);
        const uint32_t bAddr = sb + SM_B + (uint32_t)g * ROWB + tg * 8;

        auto stageA = [&](int t, int bi) {
            int img = t / TPI, tt = t - img * TPI;
            size_t row0 = (size_t)GUARD + (size_t)img * IMG_ROWS + (size_t)tt * 128 - 59;
            uint32_t dst0 = sb + SM_A + (uint32_t)bi * ABUF;
            for (int i = tid; i < 246 * 8; i += 128) {
                int r = i >> 3, j = i & 7;
                cpa16(dst0 + r * ROWB + j * 16, g_spad + (row0 + r) * 128 + j * 16);
            }
        };

        if (t0 < t1) stageA(t0, 0);
        CPA_COMMIT();

        for (int t = t0; t < t1; t++) {
            int bi = (t - t0) & 1;
            if (t + 1 < t1) { stageA(t + 1, bi ^ 1); CPA_COMMIT(); CPA_WAIT1(); }
            else            { CPA_WAIT0(); }
            asm volatile("bar.sync 1, 128;" ::: "memory");

            const uint32_t aAddr = sb + SM_A + (uint32_t)bi * ABUF
                                 + (uint32_t)(m0 + g) * ROWB + tg * 8;
            int img = t / TPI, tt = t - img * TPI;

            int c[2][5][4];
#pragma unroll
            for (int mi = 0; mi < 2; mi++)
#pragma unroll
                for (int ni = 0; ni < 5; ni++)
#pragma unroll
                    for (int r = 0; r < 4; r++) c[mi][ni][r] = 0;

            for (int tap = 0; tap < 9; tap++) {
                const uint32_t at = aAddr + (uint32_t)((tap / 3) * 58 + (tap % 3)) * ROWB;
                const uint32_t bt = bAddr + (uint32_t)(tap * NCT) * ROWB;
#pragma unroll
                for (int ks = 0; ks < 4; ks++) {
                    uint32_t a[2][4];
#pragma unroll
                    for (int mi = 0; mi < 2; mi++) {
                        uint32_t lo = at + mi * (16 * ROWB) + ks * 32;
                        asm volatile("ld.shared.v2.b32 {%0,%1}, [%2];"
                                     : "=r"(a[mi][0]), "=r"(a[mi][2]) : "r"(lo));
                        asm volatile("ld.shared.v2.b32 {%0,%1}, [%2];"
                                     : "=r"(a[mi][1]), "=r"(a[mi][3]) : "r"(lo + 8 * ROWB));
                    }
#pragma unroll
                    for (int ni = 0; ni < 5; ni++) {
                        uint32_t b0, b1;
                        asm volatile("ld.shared.v2.b32 {%0,%1}, [%2];"
                                     : "=r"(b0), "=r"(b1) : "r"(bt + ni * (8 * ROWB) + ks * 32));
#pragma unroll
                        for (int mi = 0; mi < 2; mi++) {
                            asm volatile(
                                "mma.sync.aligned.m16n8k32.row.col.s32.s8.s8.s32 "
                                "{%0,%1,%2,%3}, {%4,%5,%6,%7}, {%8,%9}, {%0,%1,%2,%3};"
                                : "+r"(c[mi][ni][0]), "+r"(c[mi][ni][1]),
                                  "+r"(c[mi][ni][2]), "+r"(c[mi][ni][3])
                                : "r"(a[mi][0]), "r"(a[mi][1]), "r"(a[mi][2]), "r"(a[mi][3]),
                                  "r"(b0), "r"(b1));
                        }
                    }
                }
            }
            size_t base = (size_t)img * C * HW;
#pragma unroll
            for (int mi = 0; mi < 2; mi++) {
#pragma unroll
                for (int half = 0; half < 2; half++) {
                    int row = m0 + mi * 16 + half * 8 + g;
                    int pos = tt * 128 + row;
                    int prow = pos / PROW, pcol = pos - prow * PROW;
                    if (pos < PIMG && prow >= 1 && prow <= 56 && pcol >= 1 && pcol <= 56) {
                        size_t off = base + (size_t)(prow - 1) * W + (pcol - 1);
#pragma unroll
                        for (int ni = 0; ni < 5; ni++) {
                            int co = ni * 8 + tg * 2;
                            size_t o0 = off + (size_t)co * HW;
                            float r0 = __ldg(x + o0), r1 = __ldg(x + o0 + HW);
                            out[o0] = fmaf((float)c[mi][ni][half * 2], abn[co], abn[NCT + co]) + r0;
                            out[o0 + HW] = fmaf((float)c[mi][ni][half * 2 + 1], abn[co + 1], abn[NCT + co + 1]) + r1;
                        }
                    }
                }
            }
            asm volatile("bar.sync 1, 128;" ::: "memory");
        }
    } else {
        // ========== SCALAR GROUP: 20 warps (640 lanes), co 40..127 ==========
        // chunk = sl/128 (5 chunks: co counts 18,18,18,17,17), pos = sl%128,
        // active lanes: pos < 112 (2 rows x 56 w).
        const int sl = tid - 128;               // 0..639
        const int chunk = sl >> 7;              // 0..4
        const int pos0 = sl & 127;
        const bool active = (pos0 < 112);
        const int pos = active ? pos0 : 0;
        const int rowsel = pos / 56;
        const int w = pos - rowsel * 56;
        const int co0 = NCT + chunk * 18 - ((chunk > 3) ? (chunk - 3) : 0);
        const int cnt = (chunk < 3) ? 18 : 17;

        const int p0 = (int)(((long)cta * NPAIR) / GRID_CONV);
        const int p1 = (int)(((long)(cta + 1) * NPAIR) / GRID_CONV);
        const uint4* s_w = (const uint4*)(smem + SM_W);
        const float4* s_cc = (const float4*)(smem + SM_CC);
        const float* s_q2 = (const float*)(smem + SM_Q2);

        float q0f = (w == 0) ? 1.0f : 0.0f;
        float q2f = (w == 55) ? 1.0f : 0.0f;

        auto stageX = [&](int p, int bi) {
            int img = p / 28, pr = p - img * 28;
            int hbase = pr * 2;
            uint32_t dst0 = sb + SM_X + (uint32_t)bi * XBUF;
            for (int i = sl; i < 4 * 58; i += 640) {
                int r = i / 58, cw = i - r * 58 - 1;
                int hr = hbase - 1 + r;
                bool ok = (hr >= 0 && hr < 56 && cw >= 0 && cw < 56);
                int hc = ok ? hr : 0, wc2 = ok ? cw : 0;
                cpa16z(dst0 + i * 16,
                       &g_xbits[(size_t)img * HW + hc * W + wc2], ok ? 16 : 0);
            }
        };

        if (p0 < p1) stageX(p0, 0);
        CPA_COMMIT();

        for (int p = p0; p < p1; p++) {
            int bi = (p - p0) & 1;
            if (p + 1 < p1) { stageX(p + 1, bi ^ 1); CPA_COMMIT(); CPA_WAIT1(); }
            else            { CPA_WAIT0(); }
            asm volatile("bar.sync 2, 640;" ::: "memory");

            const uint4* s_x = (const uint4*)(smem + SM_X + bi * XBUF);
            int img = p / 28, pr = p - img * 28;
            int h = pr * 2 + rowsel;
            int cl = (h == 0) ? 0 : ((h == 55) ? 2 : 1);
            float vr = 3.0f - (cl == 0 ? 1.0f : 0.0f) - (cl == 2 ? 1.0f : 0.0f);
            float nv128 = 128.0f * vr * (3.0f - q0f - q2f);

            uint4 xv[9];
#pragma unroll
            for (int t = 0; t < 9; t++)
                xv[t] = s_x[(rowsel + t / 3) * 58 + w + (t % 3)];

            const float* resid = x + (size_t)img * C * HW + (size_t)h * W + w;
            float* outp = out + (size_t)img * C * HW + (size_t)h * W + w;

#pragma unroll 2
            for (int k = 0; k < cnt; k++) {
                int co = co0 + k;
                int ic = co - NCT;
                float r = active ? resid[(size_t)co * HW] : 0.0f;
                float4 cf = s_cc[cl * NCS + ic];
                float q2v = s_q2[cl * NCS + ic];
                int acc1 = 0, acc2 = 0;
#pragma unroll
                for (int g2 = 0; g2 < 3; g2++) {
                    uint4 wv0 = s_w[ic * 9 + 3 * g2 + 0];
                    uint4 wv1 = s_w[ic * 9 + 3 * g2 + 1];
                    uint4 wv2 = s_w[ic * 9 + 3 * g2 + 2];
                    uint32_t s0, c0, s1, c1, s2, c2, s3, c3;
                    fadd(xv[3*g2].x ^ wv0.x, xv[3*g2+1].x ^ wv1.x, xv[3*g2+2].x ^ wv2.x, s0, c0);
                    fadd(xv[3*g2].y ^ wv0.y, xv[3*g2+1].y ^ wv1.y, xv[3*g2+2].y ^ wv2.y, s1, c1);
                    fadd(xv[3*g2].z ^ wv0.z, xv[3*g2+1].z ^ wv1.z, xv[3*g2+2].z ^ wv2.z, s2, c2);
                    fadd(xv[3*g2].w ^ wv0.w, xv[3*g2+1].w ^ wv1.w, xv[3*g2+2].w ^ wv2.w, s3, c3);
                    acc1 += __popc(s0) + __popc(s1) + __popc(s2) + __popc(s3);
                    acc2 += __popc(c0) + __popc(c1) + __popc(c2) + __popc(c3);
                }
                int acc = acc1 + 2 * acc2;
                float K = fmaf(cf.y, nv128, cf.z);
                K = fmaf(q0f, cf.w, K);
                K = fmaf(q2f, q2v, K);
                if (active) outp[(size_t)co * HW] = fmaf(cf.x, (float)acc, K) + r;
            }
            asm volatile("bar.sync 2, 640;" ::: "memory");
        }
    }
}

// ---------------------------------------------------------------------------
extern "C" void kernel_launch(void* const* d_in, const int* in_sizes, int n_in,
                              void* d_out, int out_size) {
    const float* x     = (const float*)d_in[0];
    const float* wgt   = (const float*)d_in[1];
    const float* gamma = (const float*)d_in[2];
    const float* beta  = (const float*)d_in[3];
    const float* mean  = (const float*)d_in[4];
    const float* var   = (const float*)d_in[5];
    float* out = (float*)d_out;
    (void)in_sizes; (void)n_in; (void)out_size;

    cudaFuncSetAttribute(conv_kernel, cudaFuncAttributeMaxDynamicSharedMemorySize, SMEM_TOTAL);

    sign_kernel<<<NB * H, 256>>>(x);
    wprep_kernel<<<C, 128>>>(wgt, gamma, beta, mean, var);
    conv_kernel<<<GRID_CONV, NTHREADS, SMEM_TOTAL>>>(x, out);
}